// round 14
// baseline (speedup 1.0000x reference)
#include <cuda_runtime.h>
#include <cuda_bf16.h>
#include <math.h>
#include <stdint.h>

#define HEADS   8
#define PTS     4
#define CH      256
#define MAXROWS 32768

// Scratch (__device__ globals per allocation-free rule)
__device__ uint32_t g_vb[MAXROWS * CH / 2];     // v, HEAD-MAJOR [b][head][pix][32ch] bf16x2
__device__ float    g_offlg[MAXROWS * 96];      // [off(64) | logits(32)] per row
__device__ uint32_t g_attnb[MAXROWS * CH / 2];  // sampled output, row-major bf16x2
__device__ uint32_t g_Wvalp[CH * CH / 2];       // bf16x2-packed W_val
__device__ uint32_t g_Woutp[CH * CH / 2];       // bf16x2-packed W_out

// Streams/events (created before capture).
static cudaStream_t s_side = nullptr;
static cudaEvent_t  e_fork = nullptr, e_join = nullptr;
namespace {
struct StreamInit {
    StreamInit() {
        cudaStreamCreateWithFlags(&s_side, cudaStreamNonBlocking);
        cudaEventCreateWithFlags(&e_fork, cudaEventDisableTiming);
        cudaEventCreateWithFlags(&e_join, cudaEventDisableTiming);
    }
} s_init;
}

__device__ __forceinline__ uint32_t f2tf32(float x) {
    uint32_t r;
    asm("cvt.rna.tf32.f32 %0, %1;" : "=r"(r) : "f"(x));
    return r;
}
// pack2(lo, hi): lo -> bits[0:16), hi -> bits[16:32)
__device__ __forceinline__ uint32_t pack2(float lo, float hi) {
    uint32_t r;
    asm("cvt.rn.bf16x2.f32 %0, %1, %2;" : "=r"(r) : "f"(hi), "f"(lo));
    return r;
}
__device__ __forceinline__ void cpasync16(void* dst_smem, const void* src, bool pred) {
    uint32_t d = (uint32_t)__cvta_generic_to_shared(dst_smem);
    int sz = pred ? 16 : 0;
    asm volatile("cp.async.cg.shared.global [%0], [%1], 16, %2;\n"
                 :: "r"(d), "l"(src), "r"(sz));
}

// ===========================================================================
// bf16 tensor-core GEMM (m16n8k16), cp.async 3-stage (R11/R13-proven config).
//   ABF16:   A bf16 row-major (else fp32, cvt at frag read)
//   OUTBF16: C packed bf16x2, HEAD-MAJOR [b][head][pix][32] (else fp32 + resid)
//   B: pre-packed bf16x2 [K/2][N].
// Block 128x128x32, 8 warps (2m x 4n), warp tile 64x32.
// ===========================================================================
#define ALD_F 40
#define ALD_H 20
#define BLD   136
#define ASZ_F (128 * ALD_F)
#define ASZ_H (128 * ALD_H)
#define BSZ_P (16 * BLD)
#define NSTG  3

template<bool ABF16, bool OUTBF16>
__global__ __launch_bounds__(256) void gemm_bf16(
    const void* __restrict__ Av, const uint32_t* __restrict__ Bp,
    const float* __restrict__ bias, const float* __restrict__ resid,
    void* __restrict__ Cv, int M, int N, int K,
    const int* __restrict__ hp, const int* __restrict__ wp)
{
    extern __shared__ __align__(16) uint32_t smemw[];
    constexpr int ASZ = ABF16 ? ASZ_H : ASZ_F;
    uint32_t* Asm = smemw;
    uint32_t* Bsm = smemw + NSTG * ASZ;

    const int tid  = threadIdx.x;
    const int lane = tid & 31;
    const int warp = tid >> 5;
    const int wm   = warp & 1;
    const int wn   = warp >> 1;
    const int m0   = blockIdx.y * 128;
    const int n0   = blockIdx.x * 128;
    const int lr   = lane >> 2;
    const int lc   = lane & 3;

    float acc[4][4][4];
#pragma unroll
    for (int i = 0; i < 4; i++)
#pragma unroll
        for (int j = 0; j < 4; j++)
#pragma unroll
            for (int v = 0; v < 4; v++) acc[i][j][v] = 0.f;

    const int nk = K >> 5;

    auto stage_load = [&](int s, int k0) {
        uint32_t* As = Asm + s * ASZ;
        uint32_t* Bs = Bsm + s * BSZ_P;
        if (ABF16) {
            const __nv_bfloat16* A = (const __nv_bfloat16*)Av;
#pragma unroll
            for (int i = 0; i < 2; i++) {
                int f = tid + i * 256;
                int r = f >> 2, c = f & 3;
                cpasync16(&As[r * ALD_H + c * 4],
                          &A[(size_t)(m0 + r) * K + k0 + c * 8], true);
            }
        } else {
            const float* A = (const float*)Av;
#pragma unroll
            for (int i = 0; i < 4; i++) {
                int f = tid + i * 256;
                int r = f >> 3, c4 = f & 7;
                cpasync16(&As[r * ALD_F + c4 * 4],
                          &A[(size_t)(m0 + r) * K + k0 + c4 * 4], true);
            }
        }
#pragma unroll
        for (int i = 0; i < 2; i++) {
            int f  = tid + i * 256;
            int kp = f >> 5;
            int c4 = f & 31;
            int n  = n0 + c4 * 4;
            cpasync16(&Bs[kp * BLD + c4 * 4],
                      &Bp[(size_t)((k0 >> 1) + kp) * N + n], n < N);
        }
        asm volatile("cp.async.commit_group;\n");
    };

    stage_load(0, 0);
    if (nk > 1) stage_load(1, 32);

    uint32_t af[2][4][4];
    uint32_t bf[2][4][2];

    auto frag_load = [&](const uint32_t* As, const uint32_t* Bs, int buf, int ks) {
#pragma unroll
        for (int ma = 0; ma < 4; ma++) {
            int r = wm * 64 + ma * 16 + lr;
            if (ABF16) {
                af[buf][ma][0] = As[r * ALD_H + (ks >> 1) + lc];
                af[buf][ma][1] = As[(r + 8) * ALD_H + (ks >> 1) + lc];
                af[buf][ma][2] = As[r * ALD_H + (ks >> 1) + 4 + lc];
                af[buf][ma][3] = As[(r + 8) * ALD_H + (ks >> 1) + 4 + lc];
            } else {
                const float* Af = (const float*)As;
                float2 a0 = *(const float2*)&Af[r * ALD_F + ks + 2 * lc];
                float2 a1 = *(const float2*)&Af[(r + 8) * ALD_F + ks + 2 * lc];
                float2 a2 = *(const float2*)&Af[r * ALD_F + ks + 8 + 2 * lc];
                float2 a3 = *(const float2*)&Af[(r + 8) * ALD_F + ks + 8 + 2 * lc];
                af[buf][ma][0] = pack2(a0.x, a0.y);
                af[buf][ma][1] = pack2(a1.x, a1.y);
                af[buf][ma][2] = pack2(a2.x, a2.y);
                af[buf][ma][3] = pack2(a3.x, a3.y);
            }
        }
#pragma unroll
        for (int na = 0; na < 4; na++) {
            int n = wn * 32 + na * 8 + lr;
            bf[buf][na][0] = Bs[((ks >> 1) + lc) * BLD + n];
            bf[buf][na][1] = Bs[((ks >> 1) + 4 + lc) * BLD + n];
        }
    };

    for (int kt = 0; kt < nk; kt++) {
        if (kt + 1 < nk) asm volatile("cp.async.wait_group 1;\n");
        else             asm volatile("cp.async.wait_group 0;\n");
        __syncthreads();
        if (kt + 2 < nk) stage_load((kt + 2) % NSTG, (kt + 2) * 32);

        const uint32_t* As = Asm + (kt % NSTG) * ASZ;
        const uint32_t* Bs = Bsm + (kt % NSTG) * BSZ_P;

        frag_load(As, Bs, 0, 0);
#pragma unroll
        for (int s = 0; s < 2; s++) {
            int cur = s & 1, nxt = cur ^ 1;
            if (s == 0) frag_load(As, Bs, nxt, 16);
#pragma unroll
            for (int ma = 0; ma < 4; ma++)
#pragma unroll
                for (int na = 0; na < 4; na++) {
                    asm volatile(
                        "mma.sync.aligned.m16n8k16.row.col.f32.bf16.bf16.f32 "
                        "{%0,%1,%2,%3}, {%4,%5,%6,%7}, {%8,%9}, {%0,%1,%2,%3};\n"
                        : "+f"(acc[ma][na][0]), "+f"(acc[ma][na][1]),
                          "+f"(acc[ma][na][2]), "+f"(acc[ma][na][3])
                        : "r"(af[cur][ma][0]), "r"(af[cur][ma][1]),
                          "r"(af[cur][ma][2]), "r"(af[cur][ma][3]),
                          "r"(bf[cur][na][0]), "r"(bf[cur][na][1]));
                }
        }
        __syncthreads();
    }

    const int HW = OUTBF16 ? (hp[0] * wp[0]) : 0;

#pragma unroll
    for (int ma = 0; ma < 4; ma++) {
        int r0 = m0 + wm * 64 + ma * 16 + lr;
        int r1 = r0 + 8;
        int b0 = 0, p0 = 0, b1 = 0, p1 = 0;
        if (OUTBF16) {
            b0 = r0 / HW; p0 = r0 - b0 * HW;
            b1 = r1 / HW; p1 = r1 - b1 * HW;
        }
#pragma unroll
        for (int na = 0; na < 4; na++) {
            int c = n0 + wn * 32 + na * 8 + lc * 2;
            if (c < N) {
                float2 bv = *(const float2*)&bias[c];
                float v00 = acc[ma][na][0] + bv.x;
                float v01 = acc[ma][na][1] + bv.y;
                float v10 = acc[ma][na][2] + bv.x;
                float v11 = acc[ma][na][3] + bv.y;
                if (OUTBF16) {
                    // head-major: [b][head=c>>5][pix][16 words], word (c&31)>>1
                    uint32_t* Cb = (uint32_t*)Cv;
                    size_t i0 = (((size_t)b0 * 8 + (c >> 5)) * HW + p0) * 16 + ((c & 31) >> 1);
                    size_t i1 = (((size_t)b1 * 8 + (c >> 5)) * HW + p1) * 16 + ((c & 31) >> 1);
                    Cb[i0] = pack2(v00, v01);
                    Cb[i1] = pack2(v10, v11);
                } else {
                    float* C = (float*)Cv;
                    if (resid) {
                        float2 r0v = *(const float2*)&resid[(size_t)r0 * N + c];
                        float2 r1v = *(const float2*)&resid[(size_t)r1 * N + c];
                        v00 += r0v.x; v01 += r0v.y;
                        v10 += r1v.x; v11 += r1v.y;
                    }
                    *(float2*)&C[(size_t)r0 * N + c] = make_float2(v00, v01);
                    *(float2*)&C[(size_t)r1 * N + c] = make_float2(v10, v11);
                }
            }
        }
    }
}

// ===========================================================================
// tf32 GEMM for offsets/logits: tile 128(M) x 96(N) x 32(K) (R9-proven).
// ===========================================================================
#define ALD2 36
#define BLD2 100
#define ASZ2 (128 * ALD2)
#define BSZ2 (32 * BLD2)
#define SMEM96 ((2 * ASZ2 + 2 * BSZ2) * 4)

__global__ __launch_bounds__(256) void gemm_tf32_96(
    const float* __restrict__ A,
    const float* __restrict__ W_off, const float* __restrict__ W_attn,
    const float* __restrict__ b_off, const float* __restrict__ b_attn,
    float* __restrict__ C, int M)
{
    constexpr int N = 96, K = 256;
    extern __shared__ __align__(16) float smem[];
    float* Asm = smem;
    float* Bsm = smem + 2 * ASZ2;

    const int tid  = threadIdx.x;
    const int lane = tid & 31;
    const int warp = tid >> 5;
    const int wm   = warp & 1;
    const int wn   = warp >> 1;
    const int m0   = blockIdx.y * 128;
    const int lr   = lane >> 2;
    const int lc   = lane & 3;

    float acc[4][3][4];
#pragma unroll
    for (int i = 0; i < 4; i++)
#pragma unroll
        for (int j = 0; j < 3; j++)
#pragma unroll
            for (int v = 0; v < 4; v++) acc[i][j][v] = 0.f;

    const int nk = K >> 5;

    auto stage_load = [&](int s, int k0) {
        float* As = Asm + s * ASZ2;
        float* Bs = Bsm + s * BSZ2;
#pragma unroll
        for (int i = 0; i < 4; i++) {
            int f  = tid + i * 256;
            int r  = f >> 3;
            int c4 = f & 7;
            cpasync16(&As[r * ALD2 + c4 * 4],
                      &A[(size_t)(m0 + r) * K + k0 + c4 * 4], true);
        }
#pragma unroll
        for (int i = 0; i < 3; i++) {
            int f   = tid + i * 256;
            int kk  = f / 24;
            int col = (f - kk * 24) * 4;
            const float* src = (col < 64)
                ? &W_off[(size_t)(k0 + kk) * 64 + col]
                : &W_attn[(size_t)(k0 + kk) * 32 + (col - 64)];
            cpasync16(&Bs[kk * BLD2 + col], src, true);
        }
        asm volatile("cp.async.commit_group;\n");
    };

    stage_load(0, 0);

    for (int kt = 0; kt < nk; kt++) {
        asm volatile("cp.async.wait_group 0;\n");
        __syncthreads();
        if (kt + 1 < nk) stage_load((kt + 1) & 1, (kt + 1) * 32);

        const float* As = Asm + (kt & 1) * ASZ2;
        const float* Bs = Bsm + (kt & 1) * BSZ2;

#pragma unroll
        for (int ks = 0; ks < 32; ks += 8) {
            uint32_t af[4][4];
#pragma unroll
            for (int ma = 0; ma < 4; ma++) {
                int r = wm * 64 + ma * 16 + lr;
                af[ma][0] = f2tf32(As[r * ALD2 + ks + lc]);
                af[ma][1] = f2tf32(As[(r + 8) * ALD2 + ks + lc]);
                af[ma][2] = f2tf32(As[r * ALD2 + ks + 4 + lc]);
                af[ma][3] = f2tf32(As[(r + 8) * ALD2 + ks + 4 + lc]);
            }
            uint32_t bfr[3][2];
#pragma unroll
            for (int na = 0; na < 3; na++) {
                int n = wn * 24 + na * 8 + lr;
                bfr[na][0] = f2tf32(Bs[(ks + lc) * BLD2 + n]);
                bfr[na][1] = f2tf32(Bs[(ks + 4 + lc) * BLD2 + n]);
            }
#pragma unroll
            for (int ma = 0; ma < 4; ma++)
#pragma unroll
                for (int na = 0; na < 3; na++) {
                    asm volatile(
                        "mma.sync.aligned.m16n8k8.row.col.f32.tf32.tf32.f32 "
                        "{%0,%1,%2,%3}, {%4,%5,%6,%7}, {%8,%9}, {%0,%1,%2,%3};\n"
                        : "+f"(acc[ma][na][0]), "+f"(acc[ma][na][1]),
                          "+f"(acc[ma][na][2]), "+f"(acc[ma][na][3])
                        : "r"(af[ma][0]), "r"(af[ma][1]), "r"(af[ma][2]), "r"(af[ma][3]),
                          "r"(bfr[na][0]), "r"(bfr[na][1]));
                }
        }
        __syncthreads();
    }

#pragma unroll
    for (int ma = 0; ma < 4; ma++) {
        int r0 = m0 + wm * 64 + ma * 16 + lr;
        int r1 = r0 + 8;
#pragma unroll
        for (int na = 0; na < 3; na++) {
            int c = wn * 24 + na * 8 + lc * 2;
            float2 bv = (c < 64) ? *(const float2*)&b_off[c]
                                 : *(const float2*)&b_attn[c - 64];
            *(float2*)&C[(size_t)r0 * N + c] =
                make_float2(acc[ma][na][0] + bv.x, acc[ma][na][1] + bv.y);
            *(float2*)&C[(size_t)r1 * N + c] =
                make_float2(acc[ma][na][2] + bv.x, acc[ma][na][3] + bv.y);
        }
    }
}

// ---------------------------------------------------------------------------
// Fused weight packing: W_val + W_out in one launch (R9-proven).
// ---------------------------------------------------------------------------
__global__ void pack_weights(const float* __restrict__ Wval, uint32_t* __restrict__ Pval,
                             const float* __restrict__ Wout, uint32_t* __restrict__ Pout)
{
    const int NPK = (CH / 2) * (CH / 4);
    int i = blockIdx.x * blockDim.x + threadIdx.x;
    const float* W = (i < NPK) ? Wval : Wout;
    uint32_t*    P = (i < NPK) ? Pval : Pout;
    int j  = (i < NPK) ? i : i - NPK;
    int kp = j / (CH / 4);
    int c  = (j - kp * (CH / 4)) * 4;
    float4 a = *(const float4*)&W[(size_t)(2 * kp) * CH + c];
    float4 b = *(const float4*)&W[(size_t)(2 * kp + 1) * CH + c];
    uint4 o;
    o.x = pack2(a.x, b.x);
    o.y = pack2(a.y, b.y);
    o.z = pack2(a.z, b.z);
    o.w = pack2(a.w, b.w);
    *(uint4*)&P[(size_t)kp * CH + c] = o;
}

// ---------------------------------------------------------------------------
// Deformable bilinear sampling over HEAD-MAJOR bf16 v, two-phase.
//  Phase 1 (128 thr): one thread per (row, head, point) -> pair-mapped weights
//    (wA0, wB0, wA1, wB1) + 2 pair-base word offsets.
//  Phase 2 (256 thr = 4 rows x 8 heads x 8 lanes): per point 2 x uint4 loads,
//    each covering a 128B x-adjacent pixel PAIR (fully coalesced across 8
//    lanes); lanes 0-3 = x0 corner, 4-7 = x1. shfl_xor(4) combines the pair.
// ---------------------------------------------------------------------------
__global__ __launch_bounds__(256, 5) void sample_kernel(
    const uint32_t* __restrict__ v, const float* __restrict__ offlg,
    uint32_t* __restrict__ outb,
    const int* __restrict__ hptr, const int* __restrict__ wptr)
{
    const int h = *hptr, w = *wptr;
    const int HW = h * w;
    const int tid = threadIdx.x;

    __shared__ float4 swgt[128];
    __shared__ int2   soff[128];

    if (tid < 128) {
        const int r    = tid >> 5;          // 0..3 row in block
        const int head = (tid >> 2) & 7;
        const int p    = tid & 3;
        const int row  = blockIdx.x * 4 + r;

        const int b  = row / HW;
        const int q  = row - b * HW;
        const int qy = q / w;
        const int qx = q - qy * w;
        (void)b;

        const float* base = offlg + row * 96;
        float4 lgv = *(const float4*)(base + 64 + head * 4);
        float mx = fmaxf(fmaxf(lgv.x, lgv.y), fmaxf(lgv.z, lgv.w));
        float e0 = __expf(lgv.x - mx), e1 = __expf(lgv.y - mx);
        float e2 = __expf(lgv.z - mx), e3 = __expf(lgv.w - mx);
        float inv = 1.f / (e0 + e1 + e2 + e3);
        float ep = (p == 0) ? e0 : (p == 1) ? e1 : (p == 2) ? e2 : e3;
        float aw = ep * inv;

        float2 of = *(const float2*)(base + head * 8 + p * 2);
        float ix = (float)qx + of.x;
        float iy = (float)qy + of.y;
        float xf = floorf(ix), yf = floorf(iy);
        int x0 = (int)xf, y0 = (int)yf;
        float wx1 = ix - xf, wy1 = iy - yf;
        float wx0 = 1.f - wx1, wy0 = 1.f - wy1;

        bool vx0 = (unsigned)x0 < (unsigned)w;
        bool vx1 = (unsigned)(x0 + 1) < (unsigned)w;
        bool vy0 = (unsigned)y0 < (unsigned)h;
        bool vy1 = (unsigned)(y0 + 1) < (unsigned)h;

        int x0c = min(max(x0, 0), w - 1);
        int x1c = min(max(x0 + 1, 0), w - 1);
        int y0c = min(max(y0, 0), h - 1);
        int y1c = min(max(y0 + 1, 0), h - 1);
        int xp  = min(max(x0, 0), w - 2);   // pair base: xp, xp+1 both in range

        float w00 = (vy0 && vx0) ? wx0 * wy0 * aw : 0.f;
        float w01 = (vy0 && vx1) ? wx1 * wy0 * aw : 0.f;
        float w10 = (vy1 && vx0) ? wx0 * wy1 * aw : 0.f;
        float w11 = (vy1 && vx1) ? wx1 * wy1 * aw : 0.f;

        // Map corner weights onto the physical pixels (xp, xp+1) actually read.
        float4 wg;
        wg.x = (x0c == xp ? w00 : 0.f) + (x1c == xp ? w01 : 0.f);       // laneA, y0
        wg.y = (x0c == xp + 1 ? w00 : 0.f) + (x1c == xp + 1 ? w01 : 0.f); // laneB, y0
        wg.z = (x0c == xp ? w10 : 0.f) + (x1c == xp ? w11 : 0.f);       // laneA, y1
        wg.w = (x0c == xp + 1 ? w10 : 0.f) + (x1c == xp + 1 ? w11 : 0.f); // laneB, y1

        // head-major pixel = 16 words; pair = 32 words = 128B
        int2 off;
        off.x = (y0c * w + xp) * 16;
        off.y = (y1c * w + xp) * 16;

        swgt[tid] = wg;
        soff[tid] = off;
    }
    __syncthreads();

    // Phase 2: 64 threads per row = 8 heads x 8 lanes
    const int rr   = tid >> 6;          // 0..3
    const int t63  = tid & 63;
    const int head = t63 >> 3;
    const int l8   = t63 & 7;
    const int row  = blockIdx.x * 4 + rr;
    const int b    = row / HW;

    const uint32_t* vb = v + ((size_t)(b * 8 + head) * HW) * 16 + l8 * 4;
    const int cb = (rr * 8 + head) * 4;
    const bool laneA = (l8 < 4);

    float acc[8];
#pragma unroll
    for (int i = 0; i < 8; i++) acc[i] = 0.f;

#pragma unroll
    for (int p = 0; p < PTS; p++) {
        float4 wg = swgt[cb + p];
        int2   of = soff[cb + p];
        float wy0s = laneA ? wg.x : wg.y;
        float wy1s = laneA ? wg.z : wg.w;

        uint4 c0 = *(const uint4*)(vb + of.x);
        uint4 c1 = *(const uint4*)(vb + of.y);

#pragma unroll
        for (int k = 0; k < 4; k++) {
            uint32_t w0 = (&c0.x)[k], w1 = (&c1.x)[k];
            float2 f0 = __bfloat1622float2(*(__nv_bfloat162*)&w0);
            float2 f1 = __bfloat1622float2(*(__nv_bfloat162*)&w1);
            acc[2 * k]     = fmaf(wy0s, f0.x, acc[2 * k]);
            acc[2 * k + 1] = fmaf(wy0s, f0.y, acc[2 * k + 1]);
            acc[2 * k]     = fmaf(wy1s, f1.x, acc[2 * k]);
            acc[2 * k + 1] = fmaf(wy1s, f1.y, acc[2 * k + 1]);
        }
    }

    // Combine x0 (lanes 0-3) and x1 (lanes 4-7) partial sums.
#pragma unroll
    for (int i = 0; i < 8; i++)
        acc[i] += __shfl_xor_sync(0xFFFFFFFFu, acc[i], 4);

    if (laneA) {
        uint4 pk;
        pk.x = pack2(acc[0], acc[1]);
        pk.y = pack2(acc[2], acc[3]);
        pk.z = pack2(acc[4], acc[5]);
        pk.w = pack2(acc[6], acc[7]);
        // attn stays row-major: word = row*128 + head*16 + l8*4 (l8 = 0..3)
        *(uint4*)(outb + (row << 7) + head * 16 + l8 * 4) = pk;
    }
}

// ---------------------------------------------------------------------------

extern "C" void kernel_launch(void* const* d_in, const int* in_sizes, int n_in,
                              void* d_out, int out_size)
{
    const float* query  = (const float*)d_in[0];
    const float* value  = (const float*)d_in[1];
    const float* W_off  = (const float*)d_in[2];
    const float* b_off  = (const float*)d_in[3];
    const float* W_attn = (const float*)d_in[4];
    const float* b_attn = (const float*)d_in[5];
    const float* W_val  = (const float*)d_in[6];
    const float* b_val  = (const float*)d_in[7];
    const float* W_out  = (const float*)d_in[8];
    const float* b_out  = (const float*)d_in[9];
    const int*   hp     = (const int*)d_in[10];
    const int*   wp     = (const int*)d_in[11];
    float* out = (float*)d_out;

    const int K = in_sizes[2] / (HEADS * PTS * 2);   // 256
    const int M = in_sizes[0] / K;                   // 32768
    const int N = in_sizes[6] / K;                   // 256

    float *gofflg;
    uint32_t *gvb, *gattnb, *gWvalp, *gWoutp;
    cudaGetSymbolAddress((void**)&gvb,    g_vb);
    cudaGetSymbolAddress((void**)&gofflg, g_offlg);
    cudaGetSymbolAddress((void**)&gattnb, g_attnb);
    cudaGetSymbolAddress((void**)&gWvalp, g_Wvalp);
    cudaGetSymbolAddress((void**)&gWoutp, g_Woutp);

    // GEMM1: fp32 A, packed B, bf16 head-major out. GEMM3: bf16 A, fp32 out + resid.
    auto g1 = gemm_bf16<false, true>;
    auto g3 = gemm_bf16<true, false>;
    constexpr int SMEM_G1 = (NSTG * (ASZ_F + BSZ_P)) * 4;
    constexpr int SMEM_G3 = (NSTG * (ASZ_H + BSZ_P)) * 4;

    cudaFuncSetAttribute(gemm_tf32_96, cudaFuncAttributeMaxDynamicSharedMemorySize, SMEM96);
    cudaFuncSetAttribute(g1, cudaFuncAttributeMaxDynamicSharedMemorySize, SMEM_G1);
    cudaFuncSetAttribute(g3, cudaFuncAttributeMaxDynamicSharedMemorySize, SMEM_G3);

    // Fork: fused pack overlaps gemm_tf32_96; GEMM1 on side; sample joins both.
    cudaEventRecord(e_fork, 0);
    cudaStreamWaitEvent(s_side, e_fork, 0);

    pack_weights<<<64, 256, 0, s_side>>>(W_val, gWvalp, W_out, gWoutp);
    g1<<<dim3(N / 128, M / 128), 256, SMEM_G1, s_side>>>(
        value, gWvalp, b_val, nullptr, gvb, M, N, K, hp, wp);
    cudaEventRecord(e_join, s_side);

    gemm_tf32_96<<<dim3(1, M / 128), 256, SMEM96>>>(
        query, W_off, W_attn, b_off, b_attn, gofflg, M);

    cudaStreamWaitEvent(0, e_join, 0);
    sample_kernel<<<M / 4, 256>>>(gvb, gofflg, gattnb, hp, wp);
    g3<<<dim3(N / 128, M / 128), 256, SMEM_G3>>>(
        gattnb, gWoutp, b_out, query, out, M, N, K, nullptr, nullptr);
}

// round 15
// speedup vs baseline: 1.0784x; 1.0784x over previous
#include <cuda_runtime.h>
#include <cuda_bf16.h>
#include <math.h>
#include <stdint.h>

#define HEADS   8
#define PTS     4
#define CH      256
#define MAXROWS 32768

// Scratch (__device__ globals per allocation-free rule)
__device__ uint32_t g_vb[MAXROWS * CH / 2];     // v = value@W_val, packed bf16x2
__device__ float    g_offlg[MAXROWS * 96];      // [off(64) | logits(32)] per row
__device__ uint32_t g_attnb[MAXROWS * CH / 2];  // sampled output, packed bf16x2
__device__ uint32_t g_Wvalp[CH * CH / 2];       // bf16x2-packed W_val
__device__ uint32_t g_Woutp[CH * CH / 2];       // bf16x2-packed W_out

// Streams/events (created before capture).
static cudaStream_t s_side = nullptr;
static cudaEvent_t  e_fork = nullptr, e_join = nullptr, e_sA = nullptr, e_g3A = nullptr;
namespace {
struct StreamInit {
    StreamInit() {
        cudaStreamCreateWithFlags(&s_side, cudaStreamNonBlocking);
        cudaEventCreateWithFlags(&e_fork, cudaEventDisableTiming);
        cudaEventCreateWithFlags(&e_join, cudaEventDisableTiming);
        cudaEventCreateWithFlags(&e_sA,   cudaEventDisableTiming);
        cudaEventCreateWithFlags(&e_g3A,  cudaEventDisableTiming);
    }
} s_init;
}

__device__ __forceinline__ uint32_t f2tf32(float x) {
    uint32_t r;
    asm("cvt.rna.tf32.f32 %0, %1;" : "=r"(r) : "f"(x));
    return r;
}
// pack2(lo, hi): lo -> bits[0:16), hi -> bits[16:32)
__device__ __forceinline__ uint32_t pack2(float lo, float hi) {
    uint32_t r;
    asm("cvt.rn.bf16x2.f32 %0, %1, %2;" : "=r"(r) : "f"(hi), "f"(lo));
    return r;
}
__device__ __forceinline__ void cpasync16(void* dst_smem, const void* src, bool pred) {
    uint32_t d = (uint32_t)__cvta_generic_to_shared(dst_smem);
    int sz = pred ? 16 : 0;
    asm volatile("cp.async.cg.shared.global [%0], [%1], 16, %2;\n"
                 :: "r"(d), "l"(src), "r"(sz));
}

// ===========================================================================
// bf16 tensor-core GEMM (m16n8k16), cp.async 3-stage (R11/R13-proven config).
//   ABF16:   A bf16 row-major (else fp32, cvt at frag read)
//   OUTBF16: C packed bf16x2 (else fp32 + optional resid)
//   B: pre-packed bf16x2 [K/2][N].
// Block 128x128x32, 8 warps (2m x 4n), warp tile 64x32.
// ===========================================================================
#define ALD_F 40
#define ALD_H 20
#define BLD   136
#define ASZ_F (128 * ALD_F)
#define ASZ_H (128 * ALD_H)
#define BSZ_P (16 * BLD)
#define NSTG  3

template<bool ABF16, bool OUTBF16>
__global__ __launch_bounds__(256) void gemm_bf16(
    const void* __restrict__ Av, const uint32_t* __restrict__ Bp,
    const float* __restrict__ bias, const float* __restrict__ resid,
    void* __restrict__ Cv, int M, int N, int K)
{
    extern __shared__ __align__(16) uint32_t smemw[];
    constexpr int ASZ = ABF16 ? ASZ_H : ASZ_F;
    uint32_t* Asm = smemw;
    uint32_t* Bsm = smemw + NSTG * ASZ;

    const int tid  = threadIdx.x;
    const int lane = tid & 31;
    const int warp = tid >> 5;
    const int wm   = warp & 1;
    const int wn   = warp >> 1;
    const int m0   = blockIdx.y * 128;
    const int n0   = blockIdx.x * 128;
    const int lr   = lane >> 2;
    const int lc   = lane & 3;

    float acc[4][4][4];
#pragma unroll
    for (int i = 0; i < 4; i++)
#pragma unroll
        for (int j = 0; j < 4; j++)
#pragma unroll
            for (int v = 0; v < 4; v++) acc[i][j][v] = 0.f;

    const int nk = K >> 5;

    auto stage_load = [&](int s, int k0) {
        uint32_t* As = Asm + s * ASZ;
        uint32_t* Bs = Bsm + s * BSZ_P;
        if (ABF16) {
            const __nv_bfloat16* A = (const __nv_bfloat16*)Av;
#pragma unroll
            for (int i = 0; i < 2; i++) {
                int f = tid + i * 256;
                int r = f >> 2, c = f & 3;
                cpasync16(&As[r * ALD_H + c * 4],
                          &A[(size_t)(m0 + r) * K + k0 + c * 8], true);
            }
        } else {
            const float* A = (const float*)Av;
#pragma unroll
            for (int i = 0; i < 4; i++) {
                int f = tid + i * 256;
                int r = f >> 3, c4 = f & 7;
                cpasync16(&As[r * ALD_F + c4 * 4],
                          &A[(size_t)(m0 + r) * K + k0 + c4 * 4], true);
            }
        }
#pragma unroll
        for (int i = 0; i < 2; i++) {
            int f  = tid + i * 256;
            int kp = f >> 5;
            int c4 = f & 31;
            int n  = n0 + c4 * 4;
            cpasync16(&Bs[kp * BLD + c4 * 4],
                      &Bp[(size_t)((k0 >> 1) + kp) * N + n], n < N);
        }
        asm volatile("cp.async.commit_group;\n");
    };

    stage_load(0, 0);
    if (nk > 1) stage_load(1, 32);

    uint32_t af[2][4][4];
    uint32_t bf[2][4][2];

    auto frag_load = [&](const uint32_t* As, const uint32_t* Bs, int buf, int ks) {
#pragma unroll
        for (int ma = 0; ma < 4; ma++) {
            int r = wm * 64 + ma * 16 + lr;
            if (ABF16) {
                af[buf][ma][0] = As[r * ALD_H + (ks >> 1) + lc];
                af[buf][ma][1] = As[(r + 8) * ALD_H + (ks >> 1) + lc];
                af[buf][ma][2] = As[r * ALD_H + (ks >> 1) + 4 + lc];
                af[buf][ma][3] = As[(r + 8) * ALD_H + (ks >> 1) + 4 + lc];
            } else {
                const float* Af = (const float*)As;
                float2 a0 = *(const float2*)&Af[r * ALD_F + ks + 2 * lc];
                float2 a1 = *(const float2*)&Af[(r + 8) * ALD_F + ks + 2 * lc];
                float2 a2 = *(const float2*)&Af[r * ALD_F + ks + 8 + 2 * lc];
                float2 a3 = *(const float2*)&Af[(r + 8) * ALD_F + ks + 8 + 2 * lc];
                af[buf][ma][0] = pack2(a0.x, a0.y);
                af[buf][ma][1] = pack2(a1.x, a1.y);
                af[buf][ma][2] = pack2(a2.x, a2.y);
                af[buf][ma][3] = pack2(a3.x, a3.y);
            }
        }
#pragma unroll
        for (int na = 0; na < 4; na++) {
            int n = wn * 32 + na * 8 + lr;
            bf[buf][na][0] = Bs[((ks >> 1) + lc) * BLD + n];
            bf[buf][na][1] = Bs[((ks >> 1) + 4 + lc) * BLD + n];
        }
    };

    for (int kt = 0; kt < nk; kt++) {
        if (kt + 1 < nk) asm volatile("cp.async.wait_group 1;\n");
        else             asm volatile("cp.async.wait_group 0;\n");
        __syncthreads();
        if (kt + 2 < nk) stage_load((kt + 2) % NSTG, (kt + 2) * 32);

        const uint32_t* As = Asm + (kt % NSTG) * ASZ;
        const uint32_t* Bs = Bsm + (kt % NSTG) * BSZ_P;

        frag_load(As, Bs, 0, 0);
#pragma unroll
        for (int s = 0; s < 2; s++) {
            int cur = s & 1, nxt = cur ^ 1;
            if (s == 0) frag_load(As, Bs, nxt, 16);
#pragma unroll
            for (int ma = 0; ma < 4; ma++)
#pragma unroll
                for (int na = 0; na < 4; na++) {
                    asm volatile(
                        "mma.sync.aligned.m16n8k16.row.col.f32.bf16.bf16.f32 "
                        "{%0,%1,%2,%3}, {%4,%5,%6,%7}, {%8,%9}, {%0,%1,%2,%3};\n"
                        : "+f"(acc[ma][na][0]), "+f"(acc[ma][na][1]),
                          "+f"(acc[ma][na][2]), "+f"(acc[ma][na][3])
                        : "r"(af[cur][ma][0]), "r"(af[cur][ma][1]),
                          "r"(af[cur][ma][2]), "r"(af[cur][ma][3]),
                          "r"(bf[cur][na][0]), "r"(bf[cur][na][1]));
                }
        }
        __syncthreads();
    }

#pragma unroll
    for (int ma = 0; ma < 4; ma++) {
        int r0 = m0 + wm * 64 + ma * 16 + lr;
        int r1 = r0 + 8;
#pragma unroll
        for (int na = 0; na < 4; na++) {
            int c = n0 + wn * 32 + na * 8 + lc * 2;
            if (c < N) {
                float2 bv = *(const float2*)&bias[c];
                float v00 = acc[ma][na][0] + bv.x;
                float v01 = acc[ma][na][1] + bv.y;
                float v10 = acc[ma][na][2] + bv.x;
                float v11 = acc[ma][na][3] + bv.y;
                if (OUTBF16) {
                    uint32_t* Cb = (uint32_t*)Cv;
                    Cb[((size_t)r0 * N + c) >> 1] = pack2(v00, v01);
                    Cb[((size_t)r1 * N + c) >> 1] = pack2(v10, v11);
                } else {
                    float* C = (float*)Cv;
                    if (resid) {
                        float2 r0v = *(const float2*)&resid[(size_t)r0 * N + c];
                        float2 r1v = *(const float2*)&resid[(size_t)r1 * N + c];
                        v00 += r0v.x; v01 += r0v.y;
                        v10 += r1v.x; v11 += r1v.y;
                    }
                    *(float2*)&C[(size_t)r0 * N + c] = make_float2(v00, v01);
                    *(float2*)&C[(size_t)r1 * N + c] = make_float2(v10, v11);
                }
            }
        }
    }
}

// ===========================================================================
// tf32 GEMM for offsets/logits: tile 128(M) x 96(N) x 32(K) (R9-proven).
// ===========================================================================
#define ALD2 36
#define BLD2 100
#define ASZ2 (128 * ALD2)
#define BSZ2 (32 * BLD2)
#define SMEM96 ((2 * ASZ2 + 2 * BSZ2) * 4)

__global__ __launch_bounds__(256) void gemm_tf32_96(
    const float* __restrict__ A,
    const float* __restrict__ W_off, const float* __restrict__ W_attn,
    const float* __restrict__ b_off, const float* __restrict__ b_attn,
    float* __restrict__ C, int M)
{
    constexpr int N = 96, K = 256;
    extern __shared__ __align__(16) float smem[];
    float* Asm = smem;
    float* Bsm = smem + 2 * ASZ2;

    const int tid  = threadIdx.x;
    const int lane = tid & 31;
    const int warp = tid >> 5;
    const int wm   = warp & 1;
    const int wn   = warp >> 1;
    const int m0   = blockIdx.y * 128;
    const int lr   = lane >> 2;
    const int lc   = lane & 3;

    float acc[4][3][4];
#pragma unroll
    for (int i = 0; i < 4; i++)
#pragma unroll
        for (int j = 0; j < 3; j++)
#pragma unroll
            for (int v = 0; v < 4; v++) acc[i][j][v] = 0.f;

    const int nk = K >> 5;

    auto stage_load = [&](int s, int k0) {
        float* As = Asm + s * ASZ2;
        float* Bs = Bsm + s * BSZ2;
#pragma unroll
        for (int i = 0; i < 4; i++) {
            int f  = tid + i * 256;
            int r  = f >> 3;
            int c4 = f & 7;
            cpasync16(&As[r * ALD2 + c4 * 4],
                      &A[(size_t)(m0 + r) * K + k0 + c4 * 4], true);
        }
#pragma unroll
        for (int i = 0; i < 3; i++) {
            int f   = tid + i * 256;
            int kk  = f / 24;
            int col = (f - kk * 24) * 4;
            const float* src = (col < 64)
                ? &W_off[(size_t)(k0 + kk) * 64 + col]
                : &W_attn[(size_t)(k0 + kk) * 32 + (col - 64)];
            cpasync16(&Bs[kk * BLD2 + col], src, true);
        }
        asm volatile("cp.async.commit_group;\n");
    };

    stage_load(0, 0);

    for (int kt = 0; kt < nk; kt++) {
        asm volatile("cp.async.wait_group 0;\n");
        __syncthreads();
        if (kt + 1 < nk) stage_load((kt + 1) & 1, (kt + 1) * 32);

        const float* As = Asm + (kt & 1) * ASZ2;
        const float* Bs = Bsm + (kt & 1) * BSZ2;

#pragma unroll
        for (int ks = 0; ks < 32; ks += 8) {
            uint32_t af[4][4];
#pragma unroll
            for (int ma = 0; ma < 4; ma++) {
                int r = wm * 64 + ma * 16 + lr;
                af[ma][0] = f2tf32(As[r * ALD2 + ks + lc]);
                af[ma][1] = f2tf32(As[(r + 8) * ALD2 + ks + lc]);
                af[ma][2] = f2tf32(As[r * ALD2 + ks + 4 + lc]);
                af[ma][3] = f2tf32(As[(r + 8) * ALD2 + ks + 4 + lc]);
            }
            uint32_t bfr[3][2];
#pragma unroll
            for (int na = 0; na < 3; na++) {
                int n = wn * 24 + na * 8 + lr;
                bfr[na][0] = f2tf32(Bs[(ks + lc) * BLD2 + n]);
                bfr[na][1] = f2tf32(Bs[(ks + 4 + lc) * BLD2 + n]);
            }
#pragma unroll
            for (int ma = 0; ma < 4; ma++)
#pragma unroll
                for (int na = 0; na < 3; na++) {
                    asm volatile(
                        "mma.sync.aligned.m16n8k8.row.col.f32.tf32.tf32.f32 "
                        "{%0,%1,%2,%3}, {%4,%5,%6,%7}, {%8,%9}, {%0,%1,%2,%3};\n"
                        : "+f"(acc[ma][na][0]), "+f"(acc[ma][na][1]),
                          "+f"(acc[ma][na][2]), "+f"(acc[ma][na][3])
                        : "r"(af[ma][0]), "r"(af[ma][1]), "r"(af[ma][2]), "r"(af[ma][3]),
                          "r"(bfr[na][0]), "r"(bfr[na][1]));
                }
        }
        __syncthreads();
    }

#pragma unroll
    for (int ma = 0; ma < 4; ma++) {
        int r0 = m0 + wm * 64 + ma * 16 + lr;
        int r1 = r0 + 8;
#pragma unroll
        for (int na = 0; na < 3; na++) {
            int c = wn * 24 + na * 8 + lc * 2;
            float2 bv = (c < 64) ? *(const float2*)&b_off[c]
                                 : *(const float2*)&b_attn[c - 64];
            *(float2*)&C[(size_t)r0 * N + c] =
                make_float2(acc[ma][na][0] + bv.x, acc[ma][na][1] + bv.y);
            *(float2*)&C[(size_t)r1 * N + c] =
                make_float2(acc[ma][na][2] + bv.x, acc[ma][na][3] + bv.y);
        }
    }
}

// ---------------------------------------------------------------------------
// Fused weight packing: W_val + W_out in one launch (R9-proven).
// ---------------------------------------------------------------------------
__global__ void pack_weights(const float* __restrict__ Wval, uint32_t* __restrict__ Pval,
                             const float* __restrict__ Wout, uint32_t* __restrict__ Pout)
{
    const int NPK = (CH / 2) * (CH / 4);
    int i = blockIdx.x * blockDim.x + threadIdx.x;
    const float* W = (i < NPK) ? Wval : Wout;
    uint32_t*    P = (i < NPK) ? Pval : Pout;
    int j  = (i < NPK) ? i : i - NPK;
    int kp = j / (CH / 4);
    int c  = (j - kp * (CH / 4)) * 4;
    float4 a = *(const float4*)&W[(size_t)(2 * kp) * CH + c];
    float4 b = *(const float4*)&W[(size_t)(2 * kp + 1) * CH + c];
    uint4 o;
    o.x = pack2(a.x, b.x);
    o.y = pack2(a.y, b.y);
    o.z = pack2(a.z, b.z);
    o.w = pack2(a.w, b.w);
    *(uint4*)&P[(size_t)kp * CH + c] = o;
}

// ---------------------------------------------------------------------------
// Deformable bilinear sampling over bf16 v, two-phase, 8 rows/block
// (R13-proven). row0 allows split launches for pipelining with GEMM3.
// ---------------------------------------------------------------------------
__global__ __launch_bounds__(256, 5) void sample_kernel(
    const uint32_t* __restrict__ v, const float* __restrict__ offlg,
    uint32_t* __restrict__ outb,
    const int* __restrict__ hptr, const int* __restrict__ wptr, int row0)
{
    const int h = *hptr, w = *wptr;
    const int HW = h * w;
    const int tid = threadIdx.x;

    __shared__ float4 swgt[256];
    __shared__ int4   soff[256];

    // Phase 1: all 256 threads, one per (row, head, point)
    {
        const int r    = tid >> 5;
        const int head = (tid >> 2) & 7;
        const int p    = tid & 3;
        const int row  = row0 + blockIdx.x * 8 + r;

        const int b  = row / HW;
        const int q  = row - b * HW;
        const int qy = q / w;
        const int qx = q - qy * w;
        (void)b;

        const float* base = offlg + row * 96;
        float4 lgv = *(const float4*)(base + 64 + head * 4);
        float mx = fmaxf(fmaxf(lgv.x, lgv.y), fmaxf(lgv.z, lgv.w));
        float e0 = __expf(lgv.x - mx), e1 = __expf(lgv.y - mx);
        float e2 = __expf(lgv.z - mx), e3 = __expf(lgv.w - mx);
        float inv = 1.f / (e0 + e1 + e2 + e3);
        float ep = (p == 0) ? e0 : (p == 1) ? e1 : (p == 2) ? e2 : e3;
        float aw = ep * inv;

        float2 of = *(const float2*)(base + head * 8 + p * 2);
        float ix = (float)qx + of.x;
        float iy = (float)qy + of.y;
        float xf = floorf(ix), yf = floorf(iy);
        int x0 = (int)xf, y0 = (int)yf;
        float wx1 = ix - xf, wy1 = iy - yf;
        float wx0 = 1.f - wx1, wy0 = 1.f - wy1;

        bool vx0 = (unsigned)x0 < (unsigned)w;
        bool vx1 = (unsigned)(x0 + 1) < (unsigned)w;
        bool vy0 = (unsigned)y0 < (unsigned)h;
        bool vy1 = (unsigned)(y0 + 1) < (unsigned)h;

        int x0c = min(max(x0, 0), w - 1);
        int x1c = min(max(x0 + 1, 0), w - 1);
        int y0c = min(max(y0, 0), h - 1);
        int y1c = min(max(y0 + 1, 0), h - 1);

        float4 wg;
        wg.x = (vy0 && vx0) ? wx0 * wy0 * aw : 0.f;
        wg.y = (vy0 && vx1) ? wx1 * wy0 * aw : 0.f;
        wg.z = (vy1 && vx0) ? wx0 * wy1 * aw : 0.f;
        wg.w = (vy1 && vx1) ? wx1 * wy1 * aw : 0.f;

        int r0 = (y0c * w) << 7, r1 = (y1c * w) << 7;
        int4 off;
        off.x = r0 + (x0c << 7);
        off.y = r0 + (x1c << 7);
        off.z = r1 + (x0c << 7);
        off.w = r1 + (x1c << 7);

        swgt[tid] = wg;
        soff[tid] = off;
    }
    __syncthreads();

    // Phase 2: 32 threads per row, 4 lanes/head, 8 channels/lane
    const int rr   = tid >> 5;
    const int t31  = tid & 31;
    const int head = t31 >> 2;
    const int l4   = t31 & 3;
    const int row  = row0 + blockIdx.x * 8 + rr;
    const int b    = row / HW;

    const uint32_t* vb = v + ((b * HW) << 7) + head * 16 + l4 * 4;
    const int cb = rr * 32 + head * 4;

    float acc[8];
#pragma unroll
    for (int i = 0; i < 8; i++) acc[i] = 0.f;

#pragma unroll
    for (int p = 0; p < PTS; p++) {
        float4 wg = swgt[cb + p];
        int4   of = soff[cb + p];

        uint4 c0 = *(const uint4*)(vb + of.x);
        uint4 c1 = *(const uint4*)(vb + of.y);
        uint4 c2 = *(const uint4*)(vb + of.z);
        uint4 c3 = *(const uint4*)(vb + of.w);

#pragma unroll
        for (int k = 0; k < 4; k++) {
            uint32_t w0 = (&c0.x)[k], w1 = (&c1.x)[k], w2 = (&c2.x)[k], w3 = (&c3.x)[k];
            float2 f0 = __bfloat1622float2(*(__nv_bfloat162*)&w0);
            float2 f1 = __bfloat1622float2(*(__nv_bfloat162*)&w1);
            float2 f2 = __bfloat1622float2(*(__nv_bfloat162*)&w2);
            float2 f3 = __bfloat1622float2(*(__nv_bfloat162*)&w3);
            acc[2 * k]     = fmaf(wg.x, f0.x, acc[2 * k]);
            acc[2 * k + 1] = fmaf(wg.x, f0.y, acc[2 * k + 1]);
            acc[2 * k]     = fmaf(wg.y, f1.x, acc[2 * k]);
            acc[2 * k + 1] = fmaf(wg.y, f1.y, acc[2 * k + 1]);
            acc[2 * k]     = fmaf(wg.z, f2.x, acc[2 * k]);
            acc[2 * k + 1] = fmaf(wg.z, f2.y, acc[2 * k + 1]);
            acc[2 * k]     = fmaf(wg.w, f3.x, acc[2 * k]);
            acc[2 * k + 1] = fmaf(wg.w, f3.y, acc[2 * k + 1]);
        }
    }

    uint4 pk;
    pk.x = pack2(acc[0], acc[1]);
    pk.y = pack2(acc[2], acc[3]);
    pk.z = pack2(acc[4], acc[5]);
    pk.w = pack2(acc[6], acc[7]);
    *(uint4*)(outb + (row << 7) + head * 16 + l4 * 4) = pk;
}

// ---------------------------------------------------------------------------

extern "C" void kernel_launch(void* const* d_in, const int* in_sizes, int n_in,
                              void* d_out, int out_size)
{
    const float* query  = (const float*)d_in[0];
    const float* value  = (const float*)d_in[1];
    const float* W_off  = (const float*)d_in[2];
    const float* b_off  = (const float*)d_in[3];
    const float* W_attn = (const float*)d_in[4];
    const float* b_attn = (const float*)d_in[5];
    const float* W_val  = (const float*)d_in[6];
    const float* b_val  = (const float*)d_in[7];
    const float* W_out  = (const float*)d_in[8];
    const float* b_out  = (const float*)d_in[9];
    const int*   hp     = (const int*)d_in[10];
    const int*   wp     = (const int*)d_in[11];
    float* out = (float*)d_out;

    const int K = in_sizes[2] / (HEADS * PTS * 2);   // 256
    const int M = in_sizes[0] / K;                   // 32768
    const int N = in_sizes[6] / K;                   // 256
    const int Mh = M / 2;                            // 16384

    float *gofflg;
    uint32_t *gvb, *gattnb, *gWvalp, *gWoutp;
    cudaGetSymbolAddress((void**)&gvb,    g_vb);
    cudaGetSymbolAddress((void**)&gofflg, g_offlg);
    cudaGetSymbolAddress((void**)&gattnb, g_attnb);
    cudaGetSymbolAddress((void**)&gWvalp, g_Wvalp);
    cudaGetSymbolAddress((void**)&gWoutp, g_Woutp);

    // GEMM1: fp32 A, packed B, bf16 out. GEMM3: bf16 A, packed B, fp32 out + resid.
    auto g1 = gemm_bf16<false, true>;
    auto g3 = gemm_bf16<true, false>;
    constexpr int SMEM_G1 = (NSTG * (ASZ_F + BSZ_P)) * 4;
    constexpr int SMEM_G3 = (NSTG * (ASZ_H + BSZ_P)) * 4;

    cudaFuncSetAttribute(gemm_tf32_96, cudaFuncAttributeMaxDynamicSharedMemorySize, SMEM96);
    cudaFuncSetAttribute(g1, cudaFuncAttributeMaxDynamicSharedMemorySize, SMEM_G1);
    cudaFuncSetAttribute(g3, cudaFuncAttributeMaxDynamicSharedMemorySize, SMEM_G3);

    // Fork: fused pack + GEMM1 on side; offsets GEMM on main.
    cudaEventRecord(e_fork, 0);
    cudaStreamWaitEvent(s_side, e_fork, 0);

    pack_weights<<<64, 256, 0, s_side>>>(W_val, gWvalp, W_out, gWoutp);
    g1<<<dim3(N / 128, M / 128), 256, SMEM_G1, s_side>>>(
        value, gWvalp, b_val, nullptr, gvb, M, N, K);
    cudaEventRecord(e_join, s_side);

    gemm_tf32_96<<<dim3(1, M / 128), 256, SMEM96>>>(
        query, W_off, W_attn, b_off, b_attn, gofflg, M);

    // Join, then split pipeline: sample half A -> (g3 half A on side ||
    // sample half B on main) -> g3 half B on main; main waits for side.
    cudaStreamWaitEvent(0, e_join, 0);

    sample_kernel<<<Mh / 8, 256>>>(gvb, gofflg, gattnb, hp, wp, 0);
    cudaEventRecord(e_sA, 0);

    cudaStreamWaitEvent(s_side, e_sA, 0);
    g3<<<dim3(N / 128, Mh / 128), 256, SMEM_G3, s_side>>>(
        gattnb, gWoutp, b_out, query, out, Mh, N, K);
    cudaEventRecord(e_g3A, s_side);

    sample_kernel<<<Mh / 8, 256>>>(gvb, gofflg, gattnb, hp, wp, Mh);
    g3<<<dim3(N / 128, Mh / 128), 256, SMEM_G3>>>(
        gattnb + (size_t)Mh * 128, gWoutp, b_out,
        query + (size_t)Mh * 256, out + (size_t)Mh * 256, Mh, N, K);

    cudaStreamWaitEvent(0, e_g3A, 0);
}

// round 16
// speedup vs baseline: 1.0955x; 1.0159x over previous
#include <cuda_runtime.h>
#include <cuda_bf16.h>
#include <math.h>
#include <stdint.h>

#define HEADS   8
#define PTS     4
#define CH      256
#define MAXROWS 32768

// Scratch (__device__ globals per allocation-free rule)
__device__ uint32_t g_vb[MAXROWS * CH / 2];     // v = value@W_val, packed bf16x2
__device__ float    g_offlg[MAXROWS * 96];      // [off(64) | logits(32)] per row
__device__ uint32_t g_attnb[MAXROWS * CH / 2];  // sampled output, packed bf16x2
__device__ uint32_t g_Wvalp[CH * CH / 2];       // bf16x2-packed W_val
__device__ uint32_t g_Woutp[CH * CH / 2];       // bf16x2-packed W_out

// Streams/events (created before capture).
static cudaStream_t s_side = nullptr;
static cudaEvent_t  e_fork = nullptr, e_v0 = nullptr, e_v1 = nullptr,
                    e_sA = nullptr, e_g3A = nullptr;
namespace {
struct StreamInit {
    StreamInit() {
        cudaStreamCreateWithFlags(&s_side, cudaStreamNonBlocking);
        cudaEventCreateWithFlags(&e_fork, cudaEventDisableTiming);
        cudaEventCreateWithFlags(&e_v0,   cudaEventDisableTiming);
        cudaEventCreateWithFlags(&e_v1,   cudaEventDisableTiming);
        cudaEventCreateWithFlags(&e_sA,   cudaEventDisableTiming);
        cudaEventCreateWithFlags(&e_g3A,  cudaEventDisableTiming);
    }
} s_init;
}

__device__ __forceinline__ uint32_t f2tf32(float x) {
    uint32_t r;
    asm("cvt.rna.tf32.f32 %0, %1;" : "=r"(r) : "f"(x));
    return r;
}
// pack2(lo, hi): lo -> bits[0:16), hi -> bits[16:32)
__device__ __forceinline__ uint32_t pack2(float lo, float hi) {
    uint32_t r;
    asm("cvt.rn.bf16x2.f32 %0, %1, %2;" : "=r"(r) : "f"(hi), "f"(lo));
    return r;
}
__device__ __forceinline__ void cpasync16(void* dst_smem, const void* src, bool pred) {
    uint32_t d = (uint32_t)__cvta_generic_to_shared(dst_smem);
    int sz = pred ? 16 : 0;
    asm volatile("cp.async.cg.shared.global [%0], [%1], 16, %2;\n"
                 :: "r"(d), "l"(src), "r"(sz));
}

// ===========================================================================
// bf16 tensor-core GEMM (m16n8k16), cp.async 3-stage (R11/R13-proven config).
//   ABF16:   A bf16 row-major (else fp32, cvt at frag read)
//   OUTBF16: C packed bf16x2 (else fp32 + optional resid)
//   B: pre-packed bf16x2 [K/2][N].
// Block 128x128x32, 8 warps (2m x 4n), warp tile 64x32.
// ===========================================================================
#define ALD_F 40
#define ALD_H 20
#define BLD   136
#define ASZ_F (128 * ALD_F)
#define ASZ_H (128 * ALD_H)
#define BSZ_P (16 * BLD)
#define NSTG  3

template<bool ABF16, bool OUTBF16>
__global__ __launch_bounds__(256) void gemm_bf16(
    const void* __restrict__ Av, const uint32_t* __restrict__ Bp,
    const float* __restrict__ bias, const float* __restrict__ resid,
    void* __restrict__ Cv, int M, int N, int K)
{
    extern __shared__ __align__(16) uint32_t smemw[];
    constexpr int ASZ = ABF16 ? ASZ_H : ASZ_F;
    uint32_t* Asm = smemw;
    uint32_t* Bsm = smemw + NSTG * ASZ;

    const int tid  = threadIdx.x;
    const int lane = tid & 31;
    const int warp = tid >> 5;
    const int wm   = warp & 1;
    const int wn   = warp >> 1;
    const int m0   = blockIdx.y * 128;
    const int n0   = blockIdx.x * 128;
    const int lr   = lane >> 2;
    const int lc   = lane & 3;

    float acc[4][4][4];
#pragma unroll
    for (int i = 0; i < 4; i++)
#pragma unroll
        for (int j = 0; j < 4; j++)
#pragma unroll
            for (int v = 0; v < 4; v++) acc[i][j][v] = 0.f;

    const int nk = K >> 5;

    auto stage_load = [&](int s, int k0) {
        uint32_t* As = Asm + s * ASZ;
        uint32_t* Bs = Bsm + s * BSZ_P;
        if (ABF16) {
            const __nv_bfloat16* A = (const __nv_bfloat16*)Av;
#pragma unroll
            for (int i = 0; i < 2; i++) {
                int f = tid + i * 256;
                int r = f >> 2, c = f & 3;
                cpasync16(&As[r * ALD_H + c * 4],
                          &A[(size_t)(m0 + r) * K + k0 + c * 8], true);
            }
        } else {
            const float* A = (const float*)Av;
#pragma unroll
            for (int i = 0; i < 4; i++) {
                int f = tid + i * 256;
                int r = f >> 3, c4 = f & 7;
                cpasync16(&As[r * ALD_F + c4 * 4],
                          &A[(size_t)(m0 + r) * K + k0 + c4 * 4], true);
            }
        }
#pragma unroll
        for (int i = 0; i < 2; i++) {
            int f  = tid + i * 256;
            int kp = f >> 5;
            int c4 = f & 31;
            int n  = n0 + c4 * 4;
            cpasync16(&Bs[kp * BLD + c4 * 4],
                      &Bp[(size_t)((k0 >> 1) + kp) * N + n], n < N);
        }
        asm volatile("cp.async.commit_group;\n");
    };

    stage_load(0, 0);
    if (nk > 1) stage_load(1, 32);

    uint32_t af[2][4][4];
    uint32_t bf[2][4][2];

    auto frag_load = [&](const uint32_t* As, const uint32_t* Bs, int buf, int ks) {
#pragma unroll
        for (int ma = 0; ma < 4; ma++) {
            int r = wm * 64 + ma * 16 + lr;
            if (ABF16) {
                af[buf][ma][0] = As[r * ALD_H + (ks >> 1) + lc];
                af[buf][ma][1] = As[(r + 8) * ALD_H + (ks >> 1) + lc];
                af[buf][ma][2] = As[r * ALD_H + (ks >> 1) + 4 + lc];
                af[buf][ma][3] = As[(r + 8) * ALD_H + (ks >> 1) + 4 + lc];
            } else {
                const float* Af = (const float*)As;
                float2 a0 = *(const float2*)&Af[r * ALD_F + ks + 2 * lc];
                float2 a1 = *(const float2*)&Af[(r + 8) * ALD_F + ks + 2 * lc];
                float2 a2 = *(const float2*)&Af[r * ALD_F + ks + 8 + 2 * lc];
                float2 a3 = *(const float2*)&Af[(r + 8) * ALD_F + ks + 8 + 2 * lc];
                af[buf][ma][0] = pack2(a0.x, a0.y);
                af[buf][ma][1] = pack2(a1.x, a1.y);
                af[buf][ma][2] = pack2(a2.x, a2.y);
                af[buf][ma][3] = pack2(a3.x, a3.y);
            }
        }
#pragma unroll
        for (int na = 0; na < 4; na++) {
            int n = wn * 32 + na * 8 + lr;
            bf[buf][na][0] = Bs[((ks >> 1) + lc) * BLD + n];
            bf[buf][na][1] = Bs[((ks >> 1) + 4 + lc) * BLD + n];
        }
    };

    for (int kt = 0; kt < nk; kt++) {
        if (kt + 1 < nk) asm volatile("cp.async.wait_group 1;\n");
        else             asm volatile("cp.async.wait_group 0;\n");
        __syncthreads();
        if (kt + 2 < nk) stage_load((kt + 2) % NSTG, (kt + 2) * 32);

        const uint32_t* As = Asm + (kt % NSTG) * ASZ;
        const uint32_t* Bs = Bsm + (kt % NSTG) * BSZ_P;

        frag_load(As, Bs, 0, 0);
#pragma unroll
        for (int s = 0; s < 2; s++) {
            int cur = s & 1, nxt = cur ^ 1;
            if (s == 0) frag_load(As, Bs, nxt, 16);
#pragma unroll
            for (int ma = 0; ma < 4; ma++)
#pragma unroll
                for (int na = 0; na < 4; na++) {
                    asm volatile(
                        "mma.sync.aligned.m16n8k16.row.col.f32.bf16.bf16.f32 "
                        "{%0,%1,%2,%3}, {%4,%5,%6,%7}, {%8,%9}, {%0,%1,%2,%3};\n"
                        : "+f"(acc[ma][na][0]), "+f"(acc[ma][na][1]),
                          "+f"(acc[ma][na][2]), "+f"(acc[ma][na][3])
                        : "r"(af[cur][ma][0]), "r"(af[cur][ma][1]),
                          "r"(af[cur][ma][2]), "r"(af[cur][ma][3]),
                          "r"(bf[cur][na][0]), "r"(bf[cur][na][1]));
                }
        }
        __syncthreads();
    }

#pragma unroll
    for (int ma = 0; ma < 4; ma++) {
        int r0 = m0 + wm * 64 + ma * 16 + lr;
        int r1 = r0 + 8;
#pragma unroll
        for (int na = 0; na < 4; na++) {
            int c = n0 + wn * 32 + na * 8 + lc * 2;
            if (c < N) {
                float2 bv = *(const float2*)&bias[c];
                float v00 = acc[ma][na][0] + bv.x;
                float v01 = acc[ma][na][1] + bv.y;
                float v10 = acc[ma][na][2] + bv.x;
                float v11 = acc[ma][na][3] + bv.y;
                if (OUTBF16) {
                    uint32_t* Cb = (uint32_t*)Cv;
                    Cb[((size_t)r0 * N + c) >> 1] = pack2(v00, v01);
                    Cb[((size_t)r1 * N + c) >> 1] = pack2(v10, v11);
                } else {
                    float* C = (float*)Cv;
                    if (resid) {
                        float2 r0v = *(const float2*)&resid[(size_t)r0 * N + c];
                        float2 r1v = *(const float2*)&resid[(size_t)r1 * N + c];
                        v00 += r0v.x; v01 += r0v.y;
                        v10 += r1v.x; v11 += r1v.y;
                    }
                    *(float2*)&C[(size_t)r0 * N + c] = make_float2(v00, v01);
                    *(float2*)&C[(size_t)r1 * N + c] = make_float2(v10, v11);
                }
            }
        }
    }
}

// ===========================================================================
// tf32 GEMM for offsets/logits: tile 128(M) x 96(N) x 32(K) (R9-proven).
// ===========================================================================
#define ALD2 36
#define BLD2 100
#define ASZ2 (128 * ALD2)
#define BSZ2 (32 * BLD2)
#define SMEM96 ((2 * ASZ2 + 2 * BSZ2) * 4)

__global__ __launch_bounds__(256) void gemm_tf32_96(
    const float* __restrict__ A,
    const float* __restrict__ W_off, const float* __restrict__ W_attn,
    const float* __restrict__ b_off, const float* __restrict__ b_attn,
    float* __restrict__ C, int M)
{
    constexpr int N = 96, K = 256;
    extern __shared__ __align__(16) float smem[];
    float* Asm = smem;
    float* Bsm = smem + 2 * ASZ2;

    const int tid  = threadIdx.x;
    const int lane = tid & 31;
    const int warp = tid >> 5;
    const int wm   = warp & 1;
    const int wn   = warp >> 1;
    const int m0   = blockIdx.y * 128;
    const int lr   = lane >> 2;
    const int lc   = lane & 3;

    float acc[4][3][4];
#pragma unroll
    for (int i = 0; i < 4; i++)
#pragma unroll
        for (int j = 0; j < 3; j++)
#pragma unroll
            for (int v = 0; v < 4; v++) acc[i][j][v] = 0.f;

    const int nk = K >> 5;

    auto stage_load = [&](int s, int k0) {
        float* As = Asm + s * ASZ2;
        float* Bs = Bsm + s * BSZ2;
#pragma unroll
        for (int i = 0; i < 4; i++) {
            int f  = tid + i * 256;
            int r  = f >> 3;
            int c4 = f & 7;
            cpasync16(&As[r * ALD2 + c4 * 4],
                      &A[(size_t)(m0 + r) * K + k0 + c4 * 4], true);
        }
#pragma unroll
        for (int i = 0; i < 3; i++) {
            int f   = tid + i * 256;
            int kk  = f / 24;
            int col = (f - kk * 24) * 4;
            const float* src = (col < 64)
                ? &W_off[(size_t)(k0 + kk) * 64 + col]
                : &W_attn[(size_t)(k0 + kk) * 32 + (col - 64)];
            cpasync16(&Bs[kk * BLD2 + col], src, true);
        }
        asm volatile("cp.async.commit_group;\n");
    };

    stage_load(0, 0);

    for (int kt = 0; kt < nk; kt++) {
        asm volatile("cp.async.wait_group 0;\n");
        __syncthreads();
        if (kt + 1 < nk) stage_load((kt + 1) & 1, (kt + 1) * 32);

        const float* As = Asm + (kt & 1) * ASZ2;
        const float* Bs = Bsm + (kt & 1) * BSZ2;

#pragma unroll
        for (int ks = 0; ks < 32; ks += 8) {
            uint32_t af[4][4];
#pragma unroll
            for (int ma = 0; ma < 4; ma++) {
                int r = wm * 64 + ma * 16 + lr;
                af[ma][0] = f2tf32(As[r * ALD2 + ks + lc]);
                af[ma][1] = f2tf32(As[(r + 8) * ALD2 + ks + lc]);
                af[ma][2] = f2tf32(As[r * ALD2 + ks + 4 + lc]);
                af[ma][3] = f2tf32(As[(r + 8) * ALD2 + ks + 4 + lc]);
            }
            uint32_t bfr[3][2];
#pragma unroll
            for (int na = 0; na < 3; na++) {
                int n = wn * 24 + na * 8 + lr;
                bfr[na][0] = f2tf32(Bs[(ks + lc) * BLD2 + n]);
                bfr[na][1] = f2tf32(Bs[(ks + 4 + lc) * BLD2 + n]);
            }
#pragma unroll
            for (int ma = 0; ma < 4; ma++)
#pragma unroll
                for (int na = 0; na < 3; na++) {
                    asm volatile(
                        "mma.sync.aligned.m16n8k8.row.col.f32.tf32.tf32.f32 "
                        "{%0,%1,%2,%3}, {%4,%5,%6,%7}, {%8,%9}, {%0,%1,%2,%3};\n"
                        : "+f"(acc[ma][na][0]), "+f"(acc[ma][na][1]),
                          "+f"(acc[ma][na][2]), "+f"(acc[ma][na][3])
                        : "r"(af[ma][0]), "r"(af[ma][1]), "r"(af[ma][2]), "r"(af[ma][3]),
                          "r"(bfr[na][0]), "r"(bfr[na][1]));
                }
        }
        __syncthreads();
    }

#pragma unroll
    for (int ma = 0; ma < 4; ma++) {
        int r0 = m0 + wm * 64 + ma * 16 + lr;
        int r1 = r0 + 8;
#pragma unroll
        for (int na = 0; na < 3; na++) {
            int c = wn * 24 + na * 8 + lc * 2;
            float2 bv = (c < 64) ? *(const float2*)&b_off[c]
                                 : *(const float2*)&b_attn[c - 64];
            *(float2*)&C[(size_t)r0 * N + c] =
                make_float2(acc[ma][na][0] + bv.x, acc[ma][na][1] + bv.y);
            *(float2*)&C[(size_t)r1 * N + c] =
                make_float2(acc[ma][na][2] + bv.x, acc[ma][na][3] + bv.y);
        }
    }
}

// ---------------------------------------------------------------------------
// Fused weight packing: W_val + W_out in one launch (R9-proven).
// ---------------------------------------------------------------------------
__global__ void pack_weights(const float* __restrict__ Wval, uint32_t* __restrict__ Pval,
                             const float* __restrict__ Wout, uint32_t* __restrict__ Pout)
{
    const int NPK = (CH / 2) * (CH / 4);
    int i = blockIdx.x * blockDim.x + threadIdx.x;
    const float* W = (i < NPK) ? Wval : Wout;
    uint32_t*    P = (i < NPK) ? Pval : Pout;
    int j  = (i < NPK) ? i : i - NPK;
    int kp = j / (CH / 4);
    int c  = (j - kp * (CH / 4)) * 4;
    float4 a = *(const float4*)&W[(size_t)(2 * kp) * CH + c];
    float4 b = *(const float4*)&W[(size_t)(2 * kp + 1) * CH + c];
    uint4 o;
    o.x = pack2(a.x, b.x);
    o.y = pack2(a.y, b.y);
    o.z = pack2(a.z, b.z);
    o.w = pack2(a.w, b.w);
    *(uint4*)&P[(size_t)kp * CH + c] = o;
}

// ---------------------------------------------------------------------------
// Deformable bilinear sampling over bf16 v, two-phase, 8 rows/block
// (R13-proven). row0 allows split launches for pipelining.
// ---------------------------------------------------------------------------
__global__ __launch_bounds__(256, 5) void sample_kernel(
    const uint32_t* __restrict__ v, const float* __restrict__ offlg,
    uint32_t* __restrict__ outb,
    const int* __restrict__ hptr, const int* __restrict__ wptr, int row0)
{
    const int h = *hptr, w = *wptr;
    const int HW = h * w;
    const int tid = threadIdx.x;

    __shared__ float4 swgt[256];
    __shared__ int4   soff[256];

    // Phase 1: all 256 threads, one per (row, head, point)
    {
        const int r    = tid >> 5;
        const int head = (tid >> 2) & 7;
        const int p    = tid & 3;
        const int row  = row0 + blockIdx.x * 8 + r;

        const int b  = row / HW;
        const int q  = row - b * HW;
        const int qy = q / w;
        const int qx = q - qy * w;
        (void)b;

        const float* base = offlg + row * 96;
        float4 lgv = *(const float4*)(base + 64 + head * 4);
        float mx = fmaxf(fmaxf(lgv.x, lgv.y), fmaxf(lgv.z, lgv.w));
        float e0 = __expf(lgv.x - mx), e1 = __expf(lgv.y - mx);
        float e2 = __expf(lgv.z - mx), e3 = __expf(lgv.w - mx);
        float inv = 1.f / (e0 + e1 + e2 + e3);
        float ep = (p == 0) ? e0 : (p == 1) ? e1 : (p == 2) ? e2 : e3;
        float aw = ep * inv;

        float2 of = *(const float2*)(base + head * 8 + p * 2);
        float ix = (float)qx + of.x;
        float iy = (float)qy + of.y;
        float xf = floorf(ix), yf = floorf(iy);
        int x0 = (int)xf, y0 = (int)yf;
        float wx1 = ix - xf, wy1 = iy - yf;
        float wx0 = 1.f - wx1, wy0 = 1.f - wy1;

        bool vx0 = (unsigned)x0 < (unsigned)w;
        bool vx1 = (unsigned)(x0 + 1) < (unsigned)w;
        bool vy0 = (unsigned)y0 < (unsigned)h;
        bool vy1 = (unsigned)(y0 + 1) < (unsigned)h;

        int x0c = min(max(x0, 0), w - 1);
        int x1c = min(max(x0 + 1, 0), w - 1);
        int y0c = min(max(y0, 0), h - 1);
        int y1c = min(max(y0 + 1, 0), h - 1);

        float4 wg;
        wg.x = (vy0 && vx0) ? wx0 * wy0 * aw : 0.f;
        wg.y = (vy0 && vx1) ? wx1 * wy0 * aw : 0.f;
        wg.z = (vy1 && vx0) ? wx0 * wy1 * aw : 0.f;
        wg.w = (vy1 && vx1) ? wx1 * wy1 * aw : 0.f;

        int r0 = (y0c * w) << 7, r1 = (y1c * w) << 7;
        int4 off;
        off.x = r0 + (x0c << 7);
        off.y = r0 + (x1c << 7);
        off.z = r1 + (x0c << 7);
        off.w = r1 + (x1c << 7);

        swgt[tid] = wg;
        soff[tid] = off;
    }
    __syncthreads();

    // Phase 2: 32 threads per row, 4 lanes/head, 8 channels/lane
    const int rr   = tid >> 5;
    const int t31  = tid & 31;
    const int head = t31 >> 2;
    const int l4   = t31 & 3;
    const int row  = row0 + blockIdx.x * 8 + rr;
    const int b    = row / HW;

    const uint32_t* vb = v + ((b * HW) << 7) + head * 16 + l4 * 4;
    const int cb = rr * 32 + head * 4;

    float acc[8];
#pragma unroll
    for (int i = 0; i < 8; i++) acc[i] = 0.f;

#pragma unroll
    for (int p = 0; p < PTS; p++) {
        float4 wg = swgt[cb + p];
        int4   of = soff[cb + p];

        uint4 c0 = *(const uint4*)(vb + of.x);
        uint4 c1 = *(const uint4*)(vb + of.y);
        uint4 c2 = *(const uint4*)(vb + of.z);
        uint4 c3 = *(const uint4*)(vb + of.w);

#pragma unroll
        for (int k = 0; k < 4; k++) {
            uint32_t w0 = (&c0.x)[k], w1 = (&c1.x)[k], w2 = (&c2.x)[k], w3 = (&c3.x)[k];
            float2 f0 = __bfloat1622float2(*(__nv_bfloat162*)&w0);
            float2 f1 = __bfloat1622float2(*(__nv_bfloat162*)&w1);
            float2 f2 = __bfloat1622float2(*(__nv_bfloat162*)&w2);
            float2 f3 = __bfloat1622float2(*(__nv_bfloat162*)&w3);
            acc[2 * k]     = fmaf(wg.x, f0.x, acc[2 * k]);
            acc[2 * k + 1] = fmaf(wg.x, f0.y, acc[2 * k + 1]);
            acc[2 * k]     = fmaf(wg.y, f1.x, acc[2 * k]);
            acc[2 * k + 1] = fmaf(wg.y, f1.y, acc[2 * k + 1]);
            acc[2 * k]     = fmaf(wg.z, f2.x, acc[2 * k]);
            acc[2 * k + 1] = fmaf(wg.z, f2.y, acc[2 * k + 1]);
            acc[2 * k]     = fmaf(wg.w, f3.x, acc[2 * k]);
            acc[2 * k + 1] = fmaf(wg.w, f3.y, acc[2 * k + 1]);
        }
    }

    uint4 pk;
    pk.x = pack2(acc[0], acc[1]);
    pk.y = pack2(acc[2], acc[3]);
    pk.z = pack2(acc[4], acc[5]);
    pk.w = pack2(acc[6], acc[7]);
    *(uint4*)(outb + (row << 7) + head * 16 + l4 * 4) = pk;
}

// ---------------------------------------------------------------------------

extern "C" void kernel_launch(void* const* d_in, const int* in_sizes, int n_in,
                              void* d_out, int out_size)
{
    const float* query  = (const float*)d_in[0];
    const float* value  = (const float*)d_in[1];
    const float* W_off  = (const float*)d_in[2];
    const float* b_off  = (const float*)d_in[3];
    const float* W_attn = (const float*)d_in[4];
    const float* b_attn = (const float*)d_in[5];
    const float* W_val  = (const float*)d_in[6];
    const float* b_val  = (const float*)d_in[7];
    const float* W_out  = (const float*)d_in[8];
    const float* b_out  = (const float*)d_in[9];
    const int*   hp     = (const int*)d_in[10];
    const int*   wp     = (const int*)d_in[11];
    float* out = (float*)d_out;

    const int K = in_sizes[2] / (HEADS * PTS * 2);   // 256
    const int M = in_sizes[0] / K;                   // 32768
    const int N = in_sizes[6] / K;                   // 256
    const int Mh = M / 2;                            // 16384 (= one batch)

    float *gofflg;
    uint32_t *gvb, *gattnb, *gWvalp, *gWoutp;
    cudaGetSymbolAddress((void**)&gvb,    g_vb);
    cudaGetSymbolAddress((void**)&gofflg, g_offlg);
    cudaGetSymbolAddress((void**)&gattnb, g_attnb);
    cudaGetSymbolAddress((void**)&gWvalp, g_Wvalp);
    cudaGetSymbolAddress((void**)&gWoutp, g_Woutp);

    // GEMM1: fp32 A, packed B, bf16 out. GEMM3: bf16 A, packed B, fp32 out + resid.
    auto g1 = gemm_bf16<false, true>;
    auto g3 = gemm_bf16<true, false>;
    constexpr int SMEM_G1 = (NSTG * (ASZ_F + BSZ_P)) * 4;
    constexpr int SMEM_G3 = (NSTG * (ASZ_H + BSZ_P)) * 4;

    cudaFuncSetAttribute(gemm_tf32_96, cudaFuncAttributeMaxDynamicSharedMemorySize, SMEM96);
    cudaFuncSetAttribute(g1, cudaFuncAttributeMaxDynamicSharedMemorySize, SMEM_G1);
    cudaFuncSetAttribute(g3, cudaFuncAttributeMaxDynamicSharedMemorySize, SMEM_G3);

    // Fork.
    cudaEventRecord(e_fork, 0);
    cudaStreamWaitEvent(s_side, e_fork, 0);

    // side: pack -> g1 batch0 (v rows 0..Mh) -> e_v0 -> g1 batch1 -> e_v1
    pack_weights<<<64, 256, 0, s_side>>>(W_val, gWvalp, W_out, gWoutp);
    g1<<<dim3(N / 128, Mh / 128), 256, SMEM_G1, s_side>>>(
        value, gWvalp, b_val, nullptr, gvb, Mh, N, K);
    cudaEventRecord(e_v0, s_side);
    g1<<<dim3(N / 128, Mh / 128), 256, SMEM_G1, s_side>>>(
        value + (size_t)Mh * 256, gWvalp, b_val, nullptr,
        gvb + (size_t)Mh * 128, Mh, N, K);
    cudaEventRecord(e_v1, s_side);

    // main: offsets/logits GEMM (full M)
    gemm_tf32_96<<<dim3(1, M / 128), 256, SMEM96>>>(
        query, W_off, W_attn, b_off, b_attn, gofflg, M);

    // main: sampleA (batch 0; needs v batch0 + offlg)
    cudaStreamWaitEvent(0, e_v0, 0);
    sample_kernel<<<Mh / 8, 256>>>(gvb, gofflg, gattnb, hp, wp, 0);
    cudaEventRecord(e_sA, 0);

    // side: g3 half A (overlaps sampleB on main)
    cudaStreamWaitEvent(s_side, e_sA, 0);
    g3<<<dim3(N / 128, Mh / 128), 256, SMEM_G3, s_side>>>(
        gattnb, gWoutp, b_out, query, out, Mh, N, K);
    cudaEventRecord(e_g3A, s_side);

    // main: sampleB (batch 1) then g3 half B
    cudaStreamWaitEvent(0, e_v1, 0);
    sample_kernel<<<Mh / 8, 256>>>(gvb, gofflg, gattnb, hp, wp, Mh);
    g3<<<dim3(N / 128, Mh / 128), 256, SMEM_G3>>>(
        gattnb + (size_t)Mh * 128, gWoutp, b_out,
        query + (size_t)Mh * 256, out + (size_t)Mh * 256, Mh, N, K);

    cudaStreamWaitEvent(0, e_g3A, 0);
}